// round 8
// baseline (speedup 1.0000x reference)
#include <cuda_runtime.h>
#include <cuda_bf16.h>
#include <cstdint>
#include <math.h>

// queries [16,1024,256] f32 -> M=16384, embedding [8192,256] f32 -> N=8192
// Output (f32): [M indices][M*256 quantized_st][1 vq_loss]

#define M_TOTAL 16384
#define N_TOTAL 8192
#define KDIM    256

#define BM 128
#define BN 128
#define BK 16
#define TM 8
#define TN 8
#define NBLK (N_TOTAL / BN)   // 64 column blocks

typedef unsigned long long u64;

// Scratch
__device__ float g_esq[N_TOTAL];
__device__ float g_qsq[M_TOTAL];
__device__ ulonglong2 g_btop[NBLK * M_TOTAL];
__device__ int   g_final[M_TOTAL];
__device__ float g_partial[M_TOTAL];

__device__ __forceinline__ unsigned float_ordered(float f) {
    unsigned u = __float_as_uint(f);
    return (u & 0x80000000u) ? ~u : (u | 0x80000000u);
}
__device__ __forceinline__ void ins2(u64 k, u64& m1, u64& m2) {
    if (k < m1) { m2 = m1; m1 = k; }
    else if (k < m2) { m2 = k; }
}
__device__ __forceinline__ void ins4(u64 k, u64* m) {
    if (k < m[3]) {
        if (k < m[1]) {
            if (k < m[0]) { m[3]=m[2]; m[2]=m[1]; m[1]=m[0]; m[0]=k; }
            else          { m[3]=m[2]; m[2]=m[1]; m[1]=k; }
        } else {
            if (k < m[2]) { m[3]=m[2]; m[2]=k; }
            else          { m[3]=k; }
        }
    }
}

// ---------------------------------------------------------------------------
// Squared norms: warp per row, lane-stride-32 sequential + xor tree (matches
// XLA row-reduce association; mul-then-add, NOT fused).
__global__ void sqnorm_kernel(const float* __restrict__ X, int nrows, int which) {
    int row = blockIdx.x * 8 + (threadIdx.x >> 5);
    int lane = threadIdx.x & 31;
    if (row >= nrows) return;
    const float* x = X + (size_t)row * KDIM;
    float s = 0.f;
    #pragma unroll
    for (int c = lane; c < KDIM; c += 32) { float v = x[c]; float p = v * v; s = s + p; }
    #pragma unroll
    for (int off = 16; off; off >>= 1) s += __shfl_xor_sync(0xffffffffu, s, off);
    if (lane == 0) {
        if (which) g_qsq[row] = s; else g_esq[row] = s;
    }
}

// ---------------------------------------------------------------------------
// Score GEMM (packed f32x2 FFMA2) + per-(query, colblock) top-2.
// A smem tile stores duplicated pairs {v,v} so the M-splat is a single LDS.64.
__global__ __launch_bounds__(256, 2)
void score_top2_kernel(const float* __restrict__ Q, const float* __restrict__ E) {
    __shared__ float As2[BK][2 * BM];   // [k][2m] = [k][2m+1] = A[m][k]
    __shared__ float Bs[BK][BN];

    const int tid = threadIdx.x;
    const int tx = tid & 15;
    const int ty = tid >> 4;
    const int rowBase = blockIdx.x * BM;
    const int colBase = blockIdx.y * BN;

    // packed accumulators: acc[i][jj] holds columns (tx*8+2jj, tx*8+2jj+1)
    u64 acc[TM][TN / 2];
    #pragma unroll
    for (int i = 0; i < TM; i++)
        #pragma unroll
        for (int jj = 0; jj < TN / 2; jj++) acc[i][jj] = 0ULL;

    // prefetch registers (2 float4 per matrix per tile per thread)
    float4 pa[2], pb[2];
    int pr[2], pc[2];
    #pragma unroll
    for (int l = 0; l < 2; l++) {
        int li = tid + l * 256;
        pr[l] = li >> 2;      // tile row 0..127
        pc[l] = li & 3;       // float4 index within BK=16
    }

    // load tile 0
    #pragma unroll
    for (int l = 0; l < 2; l++) {
        pa[l] = *(const float4*)(&Q[(size_t)(rowBase + pr[l]) * KDIM + pc[l] * 4]);
        pb[l] = *(const float4*)(&E[(size_t)(colBase + pr[l]) * KDIM + pc[l] * 4]);
    }

    for (int kt = 0; kt < KDIM / BK; kt++) {
        // store prefetched tile to smem
        #pragma unroll
        for (int l = 0; l < 2; l++) {
            int r = pr[l], c4 = pc[l];
            float2* a0 = (float2*)&As2[c4 * 4 + 0][2 * r];
            float2* a1 = (float2*)&As2[c4 * 4 + 1][2 * r];
            float2* a2 = (float2*)&As2[c4 * 4 + 2][2 * r];
            float2* a3 = (float2*)&As2[c4 * 4 + 3][2 * r];
            *a0 = make_float2(pa[l].x, pa[l].x);
            *a1 = make_float2(pa[l].y, pa[l].y);
            *a2 = make_float2(pa[l].z, pa[l].z);
            *a3 = make_float2(pa[l].w, pa[l].w);
            Bs[c4 * 4 + 0][r] = pb[l].x;
            Bs[c4 * 4 + 1][r] = pb[l].y;
            Bs[c4 * 4 + 2][r] = pb[l].z;
            Bs[c4 * 4 + 3][r] = pb[l].w;
        }
        __syncthreads();

        // issue next tile's global loads early
        if (kt + 1 < KDIM / BK) {
            int kn = (kt + 1) * BK;
            #pragma unroll
            for (int l = 0; l < 2; l++) {
                pa[l] = *(const float4*)(&Q[(size_t)(rowBase + pr[l]) * KDIM + kn + pc[l] * 4]);
                pb[l] = *(const float4*)(&E[(size_t)(colBase + pr[l]) * KDIM + kn + pc[l] * 4]);
            }
        }

        #pragma unroll
        for (int kk = 0; kk < BK; kk++) {
            u64 ra[TM], rb[TN / 2];
            #pragma unroll
            for (int i = 0; i < TM; i++)
                ra[i] = *(const u64*)&As2[kk][2 * (ty * TM + i)];
            #pragma unroll
            for (int jj = 0; jj < TN / 2; jj++)
                rb[jj] = *(const u64*)&Bs[kk][tx * TN + 2 * jj];
            #pragma unroll
            for (int i = 0; i < TM; i++)
                #pragma unroll
                for (int jj = 0; jj < TN / 2; jj++)
                    asm("fma.rn.f32x2 %0, %1, %2, %0;"
                        : "+l"(acc[i][jj]) : "l"(ra[i]), "l"(rb[jj]));
        }
        __syncthreads();
    }

    // Epilogue: top-2 per query row within this 128-code block.
    #pragma unroll
    for (int i = 0; i < TM; i++) {
        int grow = rowBase + ty * TM + i;
        u64 m1 = ~0ULL, m2 = ~0ULL;
        #pragma unroll
        for (int jj = 0; jj < TN / 2; jj++) {
            unsigned lo = (unsigned)(acc[i][jj] & 0xffffffffu);
            unsigned hi = (unsigned)(acc[i][jj] >> 32);
            int c0 = colBase + tx * TN + 2 * jj;
            float d0 = g_esq[c0]     - 2.0f * __uint_as_float(lo);
            float d1 = g_esq[c0 + 1] - 2.0f * __uint_as_float(hi);
            u64 k0 = ((u64)float_ordered(d0) << 32) | (unsigned)c0;
            u64 k1 = ((u64)float_ordered(d1) << 32) | (unsigned)(c0 + 1);
            ins2(k0, m1, m2);
            ins2(k1, m1, m2);
        }
        #pragma unroll
        for (int off = 8; off; off >>= 1) {
            u64 o1 = __shfl_xor_sync(0xffffffffu, m1, off, 16);
            u64 o2 = __shfl_xor_sync(0xffffffffu, m2, off, 16);
            ins2(o1, m1, m2);
            ins2(o2, m1, m2);
        }
        if (tx == 0) g_btop[blockIdx.y * M_TOTAL + grow] = make_ulonglong2(m1, m2);
    }
}

// ---------------------------------------------------------------------------
// Merge block top-2 -> global top-4; compensated-fp32 dots (~1e-8 accuracy);
// emulate the reference's fp32 rounding: d = fl32( fl32(qsq+esq) - 2*dot ).
__global__ void refine_kernel(const float* __restrict__ Q, const float* __restrict__ E) {
    int warp = threadIdx.x >> 5;
    int lane = threadIdx.x & 31;
    int q = blockIdx.x * 8 + warp;

    u64 m[4] = {~0ULL, ~0ULL, ~0ULL, ~0ULL};
    #pragma unroll
    for (int b = lane; b < NBLK; b += 32) {
        ulonglong2 v = g_btop[b * M_TOTAL + q];
        ins4(v.x, m);
        ins4(v.y, m);
    }
    #pragma unroll
    for (int off = 16; off; off >>= 1) {
        #pragma unroll
        for (int t = 0; t < 4; t++) {
            u64 o = __shfl_xor_sync(0xffffffffu, m[t], off);
            ins4(o, m);
        }
    }

    const float* qr = Q + (size_t)q * KDIM;
    float dots[4];
    int   ns[4];
    #pragma unroll
    for (int t = 0; t < 4; t++) {
        int n = (int)(unsigned)(m[t] & 0xffffffffu);
        ns[t] = n;
        const float* e = E + (size_t)n * KDIM;
        float s = 0.f, c = 0.f, err = 0.f;
        #pragma unroll
        for (int cc = lane; cc < KDIM; cc += 32) {
            float qv = qr[cc], ev = e[cc];
            float p = qv * ev;
            float r = fmaf(qv, ev, -p);   // exact product residual
            float y = p - c;              // Kahan accumulate p
            float tt = s + y;
            c = (tt - s) - y;
            s = tt;
            err += r;
        }
        #pragma unroll
        for (int off = 16; off; off >>= 1) {
            s   += __shfl_xor_sync(0xffffffffu, s, off);
            err += __shfl_xor_sync(0xffffffffu, err, off);
        }
        dots[t] = s + err;
    }

    if (lane == 0) {
        float qsq = g_qsq[q];
        u64 best = ~0ULL;
        #pragma unroll
        for (int t = 0; t < 4; t++) {
            float A = qsq + g_esq[ns[t]];        // fl32(qsq + esq)
            float d = fmaf(-2.0f, dots[t], A);   // fl32(A - 2*dot)
            u64 key = ((u64)float_ordered(d) << 32) | (unsigned)ns[t];
            best = (key < best) ? key : best;
        }
        g_final[q] = (int)(unsigned)(best & 0xffffffffu);
    }
}

// ---------------------------------------------------------------------------
__global__ void gather_kernel(const float* __restrict__ Q,
                              const float* __restrict__ E,
                              float* __restrict__ out) {
    int q = blockIdx.x;
    int idx = g_final[q];
    int c = threadIdx.x;

    float qv = Q[(size_t)q * KDIM + c];
    float ev = E[(size_t)idx * KDIM + c];
    out[(size_t)M_TOTAL + (size_t)q * KDIM + c] = qv + (ev - qv);

    float d = qv - ev;
    float s = d * d;
    #pragma unroll
    for (int off = 16; off; off >>= 1) s += __shfl_xor_sync(0xffffffffu, s, off);

    __shared__ float red[8];
    int lane = c & 31, warp = c >> 5;
    if (lane == 0) red[warp] = s;
    __syncthreads();
    if (c == 0) {
        float t = 0.f;
        #pragma unroll
        for (int w = 0; w < 8; w++) t += red[w];
        g_partial[q] = t;
        out[q] = (float)idx;
    }
}

// vq_loss = codebook + 0.25*commit = 1.25 * mean((q - quantized)^2)
__global__ void loss_kernel(float* __restrict__ out) {
    int tid = threadIdx.x;
    double s = 0.0;
    for (int i = tid; i < M_TOTAL; i += 256) s += (double)g_partial[i];
    #pragma unroll
    for (int off = 16; off; off >>= 1) s += __shfl_xor_sync(0xffffffffu, s, off);
    __shared__ double red[8];
    int lane = tid & 31, warp = tid >> 5;
    if (lane == 0) red[warp] = s;
    __syncthreads();
    if (tid == 0) {
        double t = 0.0;
        #pragma unroll
        for (int w = 0; w < 8; w++) t += red[w];
        double mean = t / (double)((size_t)M_TOTAL * KDIM);
        out[(size_t)M_TOTAL + (size_t)M_TOTAL * KDIM] = (float)(1.25 * mean);
    }
}

// ---------------------------------------------------------------------------
extern "C" void kernel_launch(void* const* d_in, const int* in_sizes, int n_in,
                              void* d_out, int out_size) {
    const float* Q = (const float*)d_in[0];
    const float* E = (const float*)d_in[1];
    float* out = (float*)d_out;

    sqnorm_kernel<<<N_TOTAL / 8, 256>>>(E, N_TOTAL, 0);
    sqnorm_kernel<<<M_TOTAL / 8, 256>>>(Q, M_TOTAL, 1);

    dim3 grid(M_TOTAL / BM, N_TOTAL / BN);  // (128, 64)
    score_top2_kernel<<<grid, 256>>>(Q, E);

    refine_kernel<<<M_TOTAL / 8, 256>>>(Q, E);
    gather_kernel<<<M_TOTAL, KDIM>>>(Q, E, out);
    loss_kernel<<<1, 256>>>(out);
}

// round 11
// speedup vs baseline: 2.0130x; 2.0130x over previous
#include <cuda_runtime.h>
#include <cuda_bf16.h>
#include <mma.h>
#include <cstdint>
#include <math.h>

using namespace nvcuda;

// queries [16,1024,256] f32 -> M=16384, embedding [8192,256] f32 -> N=8192
// Output (f32): [M indices][M*256 quantized_st][1 vq_loss]

#define M_TOTAL 16384
#define N_TOTAL 8192
#define KDIM    256
#define KC      768          // concat-K: [hi|hi|lo] x [hi|lo|hi]
#define BKC     64           // K chunk staged in smem

#define BM 128
#define BN 128
#define NBLK (N_TOTAL / BN)  // 64 column blocks
#define LDA 72               // smem row stride (bf16 units), padded

typedef unsigned long long u64;

// Scratch
__device__ float g_esq[N_TOTAL];
__device__ float g_qsq[M_TOTAL];
__device__ ulonglong2 g_btop[NBLK * M_TOTAL];
__device__ int   g_final[M_TOTAL];
__device__ float g_partial[M_TOTAL];
// concat-K bf16 operands
__device__ __nv_bfloat16 g_Qc[(size_t)M_TOTAL * KC];
__device__ __nv_bfloat16 g_Ec[(size_t)N_TOTAL * KC];

__device__ __forceinline__ unsigned float_ordered(float f) {
    unsigned u = __float_as_uint(f);
    return (u & 0x80000000u) ? ~u : (u | 0x80000000u);
}
__device__ __forceinline__ void ins2(u64 k, u64& m1, u64& m2) {
    if (k < m1) { m2 = m1; m1 = k; }
    else if (k < m2) { m2 = k; }
}
__device__ __forceinline__ void ins4(u64 k, u64* m) {
    if (k < m[3]) {
        if (k < m[1]) {
            if (k < m[0]) { m[3]=m[2]; m[2]=m[1]; m[1]=m[0]; m[0]=k; }
            else          { m[3]=m[2]; m[2]=m[1]; m[1]=k; }
        } else {
            if (k < m[2]) { m[3]=m[2]; m[2]=k; }
            else          { m[3]=k; }
        }
    }
}

// ---------------------------------------------------------------------------
// Build concat-K operands.
// Q': cols [0,256)=hi, [256,512)=hi, [512,768)=lo
// E': cols [0,256)=hi, [256,512)=lo, [512,768)=hi
__global__ void convert_q_kernel(const float* __restrict__ Q) {
    int i = blockIdx.x * 256 + threadIdx.x;
    if (i >= M_TOTAL * KDIM) return;
    int m = i >> 8, c = i & 255;
    float x = Q[i];
    __nv_bfloat16 h = __float2bfloat16(x);
    __nv_bfloat16 l = __float2bfloat16(x - __bfloat162float(h));
    size_t base = (size_t)m * KC + c;
    g_Qc[base]       = h;
    g_Qc[base + 256] = h;
    g_Qc[base + 512] = l;
}
__global__ void convert_e_kernel(const float* __restrict__ E) {
    int i = blockIdx.x * 256 + threadIdx.x;
    if (i >= N_TOTAL * KDIM) return;
    int n = i >> 8, c = i & 255;
    float x = E[i];
    __nv_bfloat16 h = __float2bfloat16(x);
    __nv_bfloat16 l = __float2bfloat16(x - __bfloat162float(h));
    size_t base = (size_t)n * KC + c;
    g_Ec[base]       = h;
    g_Ec[base + 256] = l;
    g_Ec[base + 512] = h;
}

// ---------------------------------------------------------------------------
// Squared norms (warp per row; mul-then-add + xor tree — R5-proven)
__global__ void sqnorm_kernel(const float* __restrict__ X, int nrows, int which) {
    int row = blockIdx.x * 8 + (threadIdx.x >> 5);
    int lane = threadIdx.x & 31;
    if (row >= nrows) return;
    const float* x = X + (size_t)row * KDIM;
    float s = 0.f;
    #pragma unroll
    for (int c = lane; c < KDIM; c += 32) { float v = x[c]; float p = v * v; s = s + p; }
    #pragma unroll
    for (int off = 16; off; off >>= 1) s += __shfl_xor_sync(0xffffffffu, s, off);
    if (lane == 0) { if (which) g_qsq[row] = s; else g_esq[row] = s; }
}

// ---------------------------------------------------------------------------
// wmma bf16 score GEMM over K=768 (3-product f32 emulation) + fused top-2.
// 8 warps: warp_m = wid>>2 (2), warp_n = wid&3 (4); warp tile m64 x n32.
__global__ __launch_bounds__(256, 2)
void score_wmma_kernel() {
    __shared__ union {
        struct {
            __nv_bfloat16 A[BM * LDA];
            __nv_bfloat16 B[BN * LDA];
        } s;
        float C[64 * BN];   // one 64-row half of the 128x128 result
    } sm;
    __shared__ float esq_s[BN];

    const int tid = threadIdx.x;
    const int wid = tid >> 5;
    const int wm = wid >> 2;       // 0..1
    const int wn = wid & 3;        // 0..3
    const int rowBase = blockIdx.x * BM;
    const int colBase = blockIdx.y * BN;

    if (tid < BN) esq_s[tid] = g_esq[colBase + tid];

    wmma::fragment<wmma::accumulator, 16, 16, 16, float> acc[4][2];
    #pragma unroll
    for (int i = 0; i < 4; i++)
        #pragma unroll
        for (int j = 0; j < 2; j++) wmma::fill_fragment(acc[i][j], 0.0f);

    const __nv_bfloat16* Ag = g_Qc + (size_t)rowBase * KC;
    const __nv_bfloat16* Bg = g_Ec + (size_t)colBase * KC;

    for (int kc = 0; kc < KC / BKC; kc++) {
        __syncthreads();
        // stage A,B chunk: 128 rows x 64 bf16 each (1024 x 16B per matrix)
        #pragma unroll
        for (int u = tid; u < 1024; u += 256) {
            int r = u >> 3, seg = u & 7;
            uint4 va = *(const uint4*)(Ag + (size_t)r * KC + kc * BKC + seg * 8);
            *(uint4*)(&sm.s.A[r * LDA + seg * 8]) = va;
            uint4 vb = *(const uint4*)(Bg + (size_t)r * KC + kc * BKC + seg * 8);
            *(uint4*)(&sm.s.B[r * LDA + seg * 8]) = vb;
        }
        __syncthreads();

        #pragma unroll
        for (int ks = 0; ks < BKC / 16; ks++) {
            wmma::fragment<wmma::matrix_a, 16, 16, 16, __nv_bfloat16, wmma::row_major> af[4];
            wmma::fragment<wmma::matrix_b, 16, 16, 16, __nv_bfloat16, wmma::col_major> bf[2];
            #pragma unroll
            for (int i = 0; i < 4; i++)
                wmma::load_matrix_sync(af[i],
                    &sm.s.A[(wm * 64 + i * 16) * LDA + ks * 16], LDA);
            #pragma unroll
            for (int j = 0; j < 2; j++)
                wmma::load_matrix_sync(bf[j],
                    &sm.s.B[(wn * 32 + j * 16) * LDA + ks * 16], LDA);
            #pragma unroll
            for (int i = 0; i < 4; i++)
                #pragma unroll
                for (int j = 0; j < 2; j++)
                    wmma::mma_sync(acc[i][j], af[i], bf[j], acc[i][j]);
        }
    }

    // Epilogue: two 64-row halves via smem; 4 lanes per row do top-2.
    #pragma unroll
    for (int h = 0; h < 2; h++) {
        __syncthreads();
        if (wm == h) {
            #pragma unroll
            for (int i = 0; i < 4; i++)
                #pragma unroll
                for (int j = 0; j < 2; j++)
                    wmma::store_matrix_sync(
                        &sm.C[(i * 16) * BN + wn * 32 + j * 16],
                        acc[i][j], BN, wmma::mem_row_major);
        }
        __syncthreads();

        int row = tid >> 2;         // 0..63
        int quad = tid & 3;         // 0..3
        int grow = rowBase + h * 64 + row;
        u64 m1 = ~0ULL, m2 = ~0ULL;
        #pragma unroll
        for (int j = 0; j < 32; j++) {
            int col = quad * 32 + j;
            float dist = esq_s[col] - 2.0f * sm.C[row * BN + col];
            u64 key = ((u64)float_ordered(dist) << 32) | (unsigned)(colBase + col);
            ins2(key, m1, m2);
        }
        #pragma unroll
        for (int off = 1; off < 4; off <<= 1) {
            u64 o1 = __shfl_xor_sync(0xffffffffu, m1, off, 4);
            u64 o2 = __shfl_xor_sync(0xffffffffu, m2, off, 4);
            ins2(o1, m1, m2);
            ins2(o2, m1, m2);
        }
        if (quad == 0)
            g_btop[blockIdx.y * M_TOTAL + grow] = make_ulonglong2(m1, m2);
    }
}

// ---------------------------------------------------------------------------
// Merge block top-2 -> global top-4; compensated-fp32 exact dots; emulate the
// reference's fp32 rounding: d = fl32( fl32(qsq+esq) - 2*dot ). (R8-proven)
__global__ void refine_kernel(const float* __restrict__ Q, const float* __restrict__ E) {
    int warp = threadIdx.x >> 5;
    int lane = threadIdx.x & 31;
    int q = blockIdx.x * 8 + warp;

    u64 m[4] = {~0ULL, ~0ULL, ~0ULL, ~0ULL};
    #pragma unroll
    for (int b = lane; b < NBLK; b += 32) {
        ulonglong2 v = g_btop[b * M_TOTAL + q];
        ins4(v.x, m);
        ins4(v.y, m);
    }
    #pragma unroll
    for (int off = 16; off; off >>= 1) {
        #pragma unroll
        for (int t = 0; t < 4; t++) {
            u64 o = __shfl_xor_sync(0xffffffffu, m[t], off);
            ins4(o, m);
        }
    }

    const float* qr = Q + (size_t)q * KDIM;
    float dots[4];
    int   ns[4];
    #pragma unroll
    for (int t = 0; t < 4; t++) {
        int n = (int)(unsigned)(m[t] & 0xffffffffu);
        ns[t] = n;
        const float* e = E + (size_t)n * KDIM;
        float s = 0.f, c = 0.f, err = 0.f;
        #pragma unroll
        for (int cc = lane; cc < KDIM; cc += 32) {
            float qv = qr[cc], ev = e[cc];
            float p = qv * ev;
            float r = fmaf(qv, ev, -p);
            float y = p - c;
            float tt = s + y;
            c = (tt - s) - y;
            s = tt;
            err += r;
        }
        #pragma unroll
        for (int off = 16; off; off >>= 1) {
            s   += __shfl_xor_sync(0xffffffffu, s, off);
            err += __shfl_xor_sync(0xffffffffu, err, off);
        }
        dots[t] = s + err;
    }

    if (lane == 0) {
        float qsq = g_qsq[q];
        u64 best = ~0ULL;
        #pragma unroll
        for (int t = 0; t < 4; t++) {
            float A = qsq + g_esq[ns[t]];
            float d = fmaf(-2.0f, dots[t], A);
            u64 key = ((u64)float_ordered(d) << 32) | (unsigned)ns[t];
            best = (key < best) ? key : best;
        }
        g_final[q] = (int)(unsigned)(best & 0xffffffffu);
    }
}

// ---------------------------------------------------------------------------
__global__ void gather_kernel(const float* __restrict__ Q,
                              const float* __restrict__ E,
                              float* __restrict__ out) {
    int q = blockIdx.x;
    int idx = g_final[q];
    int c = threadIdx.x;

    float qv = Q[(size_t)q * KDIM + c];
    float ev = E[(size_t)idx * KDIM + c];
    out[(size_t)M_TOTAL + (size_t)q * KDIM + c] = qv + (ev - qv);

    float d = qv - ev;
    float s = d * d;
    #pragma unroll
    for (int off = 16; off; off >>= 1) s += __shfl_xor_sync(0xffffffffu, s, off);

    __shared__ float red[8];
    int lane = c & 31, warp = c >> 5;
    if (lane == 0) red[warp] = s;
    __syncthreads();
    if (c == 0) {
        float t = 0.f;
        #pragma unroll
        for (int w = 0; w < 8; w++) t += red[w];
        g_partial[q] = t;
        out[q] = (float)idx;
    }
}

// vq_loss = codebook + 0.25*commit = 1.25 * mean((q - quantized)^2)
__global__ void loss_kernel(float* __restrict__ out) {
    int tid = threadIdx.x;
    double s = 0.0;
    for (int i = tid; i < M_TOTAL; i += 256) s += (double)g_partial[i];
    #pragma unroll
    for (int off = 16; off; off >>= 1) s += __shfl_xor_sync(0xffffffffu, s, off);
    __shared__ double red[8];
    int lane = tid & 31, warp = tid >> 5;
    if (lane == 0) red[warp] = s;
    __syncthreads();
    if (tid == 0) {
        double t = 0.0;
        #pragma unroll
        for (int w = 0; w < 8; w++) t += red[w];
        double mean = t / (double)((size_t)M_TOTAL * KDIM);
        out[(size_t)M_TOTAL + (size_t)M_TOTAL * KDIM] = (float)(1.25 * mean);
    }
}

// ---------------------------------------------------------------------------
extern "C" void kernel_launch(void* const* d_in, const int* in_sizes, int n_in,
                              void* d_out, int out_size) {
    const float* Q = (const float*)d_in[0];
    const float* E = (const float*)d_in[1];
    float* out = (float*)d_out;

    convert_q_kernel<<<(M_TOTAL * KDIM + 255) / 256, 256>>>(Q);
    convert_e_kernel<<<(N_TOTAL * KDIM + 255) / 256, 256>>>(E);

    sqnorm_kernel<<<N_TOTAL / 8, 256>>>(E, N_TOTAL, 0);
    sqnorm_kernel<<<M_TOTAL / 8, 256>>>(Q, M_TOTAL, 1);

    dim3 grid(M_TOTAL / BM, N_TOTAL / BN);  // (128, 64)
    score_wmma_kernel<<<grid, 256>>>();

    refine_kernel<<<M_TOTAL / 8, 256>>>(Q, E);
    gather_kernel<<<M_TOTAL, KDIM>>>(Q, E, out);
    loss_kernel<<<1, 256>>>(out);
}

// round 15
// speedup vs baseline: 2.1335x; 1.0599x over previous
#include <cuda_runtime.h>
#include <cuda_bf16.h>
#include <cuda_fp16.h>
#include <mma.h>
#include <cstdint>
#include <math.h>

using namespace nvcuda;

// queries [16,1024,256] f32 -> M=16384, embedding [8192,256] f32 -> N=8192
// Output (f32): [M indices][M*256 quantized_st][1 vq_loss]

#define M_TOTAL 16384
#define N_TOTAL 8192
#define KDIM    256
#define KC      512          // fp16 2-product: Q'=[hi|lo], E reads e_hi twice
#define BKC     64
#define NCHUNK  (KC / BKC)   // 8

#define BM 128
#define BN 128
#define NBLK (N_TOTAL / BN)  // 64 column blocks
#define LDA 72               // smem row stride (halves), padded

#define STAGE_BYTES (BM * LDA * 2)          // one matrix stage: 18432 B
#define SMEM_DYN    (4 * STAGE_BYTES)       // A0,B0,A1,B1 = 73728 B

typedef unsigned long long u64;

// Scratch
__device__ float g_esq[N_TOTAL];
__device__ float g_qsq[M_TOTAL];
__device__ ulonglong2 g_btop[NBLK * M_TOTAL];
__device__ int   g_final[M_TOTAL];
__device__ float g_partial[M_TOTAL];
__device__ __half g_Qc[(size_t)M_TOTAL * KC];   // [hi(256) | lo(256)]
__device__ __half g_Eh[(size_t)N_TOTAL * KDIM]; // e_hi only

__device__ __forceinline__ unsigned float_ordered(float f) {
    unsigned u = __float_as_uint(f);
    return (u & 0x80000000u) ? ~u : (u | 0x80000000u);
}
__device__ __forceinline__ void ins2(u64 k, u64& m1, u64& m2) {
    if (k < m1) { m2 = m1; m1 = k; }
    else if (k < m2) { m2 = k; }
}
__device__ __forceinline__ void ins4(u64 k, u64* m) {
    if (k < m[3]) {
        if (k < m[1]) {
            if (k < m[0]) { m[3]=m[2]; m[2]=m[1]; m[1]=m[0]; m[0]=k; }
            else          { m[3]=m[2]; m[2]=m[1]; m[1]=k; }
        } else {
            if (k < m[2]) { m[3]=m[2]; m[2]=k; }
            else          { m[3]=k; }
        }
    }
}

__device__ __forceinline__ uint32_t smem_u32(const void* p) {
    uint32_t a;
    asm("{ .reg .u64 t; cvta.to.shared.u64 t, %1; cvt.u32.u64 %0, t; }"
        : "=r"(a) : "l"(p));
    return a;
}
__device__ __forceinline__ void cp16(uint32_t dst, const void* src) {
    asm volatile("cp.async.cg.shared.global [%0], [%1], 16;"
                 :: "r"(dst), "l"(src) : "memory");
}
#define CP_COMMIT() asm volatile("cp.async.commit_group;" ::: "memory")
#define CP_WAIT(n)  asm volatile("cp.async.wait_group %0;" :: "n"(n) : "memory")

// ---------------------------------------------------------------------------
// fp16 hi/lo split for Q (concat-K), fp16 hi for E.
__global__ void convert_q_kernel(const float* __restrict__ Q) {
    int i = blockIdx.x * 256 + threadIdx.x;
    if (i >= M_TOTAL * KDIM) return;
    int m = i >> 8, c = i & 255;
    float x = Q[i];
    __half h = __float2half(x);
    __half l = __float2half(x - __half2float(h));
    size_t base = (size_t)m * KC + c;
    g_Qc[base]       = h;
    g_Qc[base + 256] = l;
}
__global__ void convert_e_kernel(const float* __restrict__ E) {
    int i = blockIdx.x * 256 + threadIdx.x;
    if (i >= N_TOTAL * KDIM) return;
    g_Eh[i] = __float2half(E[i]);
}

// ---------------------------------------------------------------------------
// Squared norms (warp per row; mul-then-add + xor tree — R5-proven)
__global__ void sqnorm_kernel(const float* __restrict__ X, int nrows, int which) {
    int row = blockIdx.x * 8 + (threadIdx.x >> 5);
    int lane = threadIdx.x & 31;
    if (row >= nrows) return;
    const float* x = X + (size_t)row * KDIM;
    float s = 0.f;
    #pragma unroll
    for (int c = lane; c < KDIM; c += 32) { float v = x[c]; float p = v * v; s = s + p; }
    #pragma unroll
    for (int off = 16; off; off >>= 1) s += __shfl_xor_sync(0xffffffffu, s, off);
    if (lane == 0) { if (which) g_qsq[row] = s; else g_esq[row] = s; }
}

// ---------------------------------------------------------------------------
// wmma fp16 score GEMM over K=512 with 2-stage cp.async pipeline + fused top-2.
// 8 warps: wm = wid>>2 (2), wn = wid&3 (4); warp tile m64 x n32.
__global__ __launch_bounds__(256, 2)
void score_wmma_kernel() {
    extern __shared__ char dsm[];
    __shared__ float esq_s[BN];

    const int tid = threadIdx.x;
    const int wid = tid >> 5;
    const int wm = wid >> 2;
    const int wn = wid & 3;
    const int rowBase = blockIdx.x * BM;
    const int colBase = blockIdx.y * BN;

    if (tid < BN) esq_s[tid] = g_esq[colBase + tid];

    __half* As[2] = { (__half*)(dsm),
                      (__half*)(dsm + 2 * STAGE_BYTES) };
    __half* Bs[2] = { (__half*)(dsm + STAGE_BYTES),
                      (__half*)(dsm + 3 * STAGE_BYTES) };
    const uint32_t asu[2] = { smem_u32(As[0]), smem_u32(As[1]) };
    const uint32_t bsu[2] = { smem_u32(Bs[0]), smem_u32(Bs[1]) };

    const __half* Ag = g_Qc + (size_t)rowBase * KC;
    const __half* Bg = g_Eh + (size_t)colBase * KDIM;

    // per-thread stage-load geometry: two threads per row; each covers 4
    // contiguous 16B segs -> all 8 segs (128 B) of every row are written.
    const int r4 = tid >> 1;          // 0..127
    const int sg = (tid & 1) * 4;     // 0 or 4

    auto load_stage = [&](int buf, int kc) {
        #pragma unroll
        for (int h = 0; h < 4; h++) {
            int seg = sg + h;        // 0..3 or 4..7
            cp16(asu[buf] + (uint32_t)(r4 * (LDA * 2) + seg * 16),
                 Ag + (size_t)r4 * KC + kc * BKC + seg * 8);
            cp16(bsu[buf] + (uint32_t)(r4 * (LDA * 2) + seg * 16),
                 Bg + (size_t)r4 * KDIM + (kc & 3) * BKC + seg * 8);
        }
    };

    wmma::fragment<wmma::accumulator, 16, 16, 16, float> acc[4][2];
    #pragma unroll
    for (int i = 0; i < 4; i++)
        #pragma unroll
        for (int j = 0; j < 2; j++) wmma::fill_fragment(acc[i][j], 0.0f);

    load_stage(0, 0);
    CP_COMMIT();

    for (int kc = 0; kc < NCHUNK; kc++) {
        if (kc + 1 < NCHUNK) {
            load_stage((kc + 1) & 1, kc + 1);
            CP_COMMIT();
            CP_WAIT(1);        // chunk kc resident
        } else {
            CP_WAIT(0);
        }
        __syncthreads();

        const __half* A = As[kc & 1];
        const __half* B = Bs[kc & 1];
        #pragma unroll
        for (int ks = 0; ks < BKC / 16; ks++) {
            wmma::fragment<wmma::matrix_a, 16, 16, 16, __half, wmma::row_major> af[4];
            wmma::fragment<wmma::matrix_b, 16, 16, 16, __half, wmma::col_major> bf[2];
            #pragma unroll
            for (int i = 0; i < 4; i++)
                wmma::load_matrix_sync(af[i], &A[(wm * 64 + i * 16) * LDA + ks * 16], LDA);
            #pragma unroll
            for (int j = 0; j < 2; j++)
                wmma::load_matrix_sync(bf[j], &B[(wn * 32 + j * 16) * LDA + ks * 16], LDA);
            #pragma unroll
            for (int i = 0; i < 4; i++)
                #pragma unroll
                for (int j = 0; j < 2; j++)
                    wmma::mma_sync(acc[i][j], af[i], bf[j], acc[i][j]);
        }
        __syncthreads();
    }

    // Epilogue: two 64-row halves via smem (reuses stage memory); top-2/row.
    float* C = (float*)dsm;   // 64 x BN floats = 32 KB < SMEM_DYN
    #pragma unroll
    for (int h = 0; h < 2; h++) {
        __syncthreads();
        if (wm == h) {
            #pragma unroll
            for (int i = 0; i < 4; i++)
                #pragma unroll
                for (int j = 0; j < 2; j++)
                    wmma::store_matrix_sync(&C[(i * 16) * BN + wn * 32 + j * 16],
                                            acc[i][j], BN, wmma::mem_row_major);
        }
        __syncthreads();

        int row = tid >> 2;
        int quad = tid & 3;
        int grow = rowBase + h * 64 + row;
        u64 m1 = ~0ULL, m2 = ~0ULL;
        #pragma unroll
        for (int j = 0; j < 32; j++) {
            int col = quad * 32 + j;
            float dist = esq_s[col] - 2.0f * C[row * BN + col];
            u64 key = ((u64)float_ordered(dist) << 32) | (unsigned)(colBase + col);
            ins2(key, m1, m2);
        }
        #pragma unroll
        for (int off = 1; off < 4; off <<= 1) {
            u64 o1 = __shfl_xor_sync(0xffffffffu, m1, off, 4);
            u64 o2 = __shfl_xor_sync(0xffffffffu, m2, off, 4);
            ins2(o1, m1, m2);
            ins2(o2, m1, m2);
        }
        if (quad == 0)
            g_btop[blockIdx.y * M_TOTAL + grow] = make_ulonglong2(m1, m2);
    }
}

// ---------------------------------------------------------------------------
// Merge block top-2 -> global top-4; compensated-fp32 exact dots; emulate the
// reference's fp32 rounding: d = fl32( fl32(qsq+esq) - 2*dot ). (proven)
__global__ void refine_kernel(const float* __restrict__ Q, const float* __restrict__ E) {
    int warp = threadIdx.x >> 5;
    int lane = threadIdx.x & 31;
    int q = blockIdx.x * 8 + warp;

    u64 m[4] = {~0ULL, ~0ULL, ~0ULL, ~0ULL};
    #pragma unroll
    for (int b = lane; b < NBLK; b += 32) {
        ulonglong2 v = g_btop[b * M_TOTAL + q];
        ins4(v.x, m);
        ins4(v.y, m);
    }
    #pragma unroll
    for (int off = 16; off; off >>= 1) {
        #pragma unroll
        for (int t = 0; t < 4; t++) {
            u64 o = __shfl_xor_sync(0xffffffffu, m[t], off);
            ins4(o, m);
        }
    }

    const float* qr = Q + (size_t)q * KDIM;
    float dots[4];
    int   ns[4];
    #pragma unroll
    for (int t = 0; t < 4; t++) {
        int n = (int)(unsigned)(m[t] & 0xffffffffu);
        ns[t] = n;
        const float* e = E + (size_t)n * KDIM;
        float s = 0.f, c = 0.f, err = 0.f;
        #pragma unroll
        for (int cc = lane; cc < KDIM; cc += 32) {
            float qv = qr[cc], ev = e[cc];
            float p = qv * ev;
            float r = fmaf(qv, ev, -p);
            float y = p - c;
            float tt = s + y;
            c = (tt - s) - y;
            s = tt;
            err += r;
        }
        #pragma unroll
        for (int off = 16; off; off >>= 1) {
            s   += __shfl_xor_sync(0xffffffffu, s, off);
            err += __shfl_xor_sync(0xffffffffu, err, off);
        }
        dots[t] = s + err;
    }

    if (lane == 0) {
        float qsq = g_qsq[q];
        u64 best = ~0ULL;
        #pragma unroll
        for (int t = 0; t < 4; t++) {
            float A = qsq + g_esq[ns[t]];
            float d = fmaf(-2.0f, dots[t], A);
            u64 key = ((u64)float_ordered(d) << 32) | (unsigned)ns[t];
            best = (key < best) ? key : best;
        }
        g_final[q] = (int)(unsigned)(best & 0xffffffffu);
    }
}

// ---------------------------------------------------------------------------
__global__ void gather_kernel(const float* __restrict__ Q,
                              const float* __restrict__ E,
                              float* __restrict__ out) {
    int q = blockIdx.x;
    int idx = g_final[q];
    int c = threadIdx.x;

    float qv = Q[(size_t)q * KDIM + c];
    float ev = E[(size_t)idx * KDIM + c];
    out[(size_t)M_TOTAL + (size_t)q * KDIM + c] = qv + (ev - qv);

    float d = qv - ev;
    float s = d * d;
    #pragma unroll
    for (int off = 16; off; off >>= 1) s += __shfl_xor_sync(0xffffffffu, s, off);

    __shared__ float red[8];
    int lane = c & 31, warp = c >> 5;
    if (lane == 0) red[warp] = s;
    __syncthreads();
    if (c == 0) {
        float t = 0.f;
        #pragma unroll
        for (int w = 0; w < 8; w++) t += red[w];
        g_partial[q] = t;
        out[q] = (float)idx;
    }
}

// vq_loss = codebook + 0.25*commit = 1.25 * mean((q - quantized)^2)
__global__ void loss_kernel(float* __restrict__ out) {
    int tid = threadIdx.x;
    double s = 0.0;
    for (int i = tid; i < M_TOTAL; i += 256) s += (double)g_partial[i];
    #pragma unroll
    for (int off = 16; off; off >>= 1) s += __shfl_xor_sync(0xffffffffu, s, off);
    __shared__ double red[8];
    int lane = tid & 31, warp = tid >> 5;
    if (lane == 0) red[warp] = s;
    __syncthreads();
    if (tid == 0) {
        double t = 0.0;
        #pragma unroll
        for (int w = 0; w < 8; w++) t += red[w];
        double mean = t / (double)((size_t)M_TOTAL * KDIM);
        out[(size_t)M_TOTAL + (size_t)M_TOTAL * KDIM] = (float)(1.25 * mean);
    }
}

// ---------------------------------------------------------------------------
extern "C" void kernel_launch(void* const* d_in, const int* in_sizes, int n_in,
                              void* d_out, int out_size) {
    const float* Q = (const float*)d_in[0];
    const float* E = (const float*)d_in[1];
    float* out = (float*)d_out;

    cudaFuncSetAttribute(score_wmma_kernel,
                         cudaFuncAttributeMaxDynamicSharedMemorySize, SMEM_DYN);

    convert_q_kernel<<<(M_TOTAL * KDIM + 255) / 256, 256>>>(Q);
    convert_e_kernel<<<(N_TOTAL * KDIM + 255) / 256, 256>>>(E);

    sqnorm_kernel<<<N_TOTAL / 8, 256>>>(E, N_TOTAL, 0);
    sqnorm_kernel<<<M_TOTAL / 8, 256>>>(Q, M_TOTAL, 1);

    dim3 grid(M_TOTAL / BM, N_TOTAL / BN);  // (128, 64)
    score_wmma_kernel<<<grid, 256, SMEM_DYN>>>();

    refine_kernel<<<M_TOTAL / 8, 256>>>(Q, E);
    gather_kernel<<<M_TOTAL, KDIM>>>(Q, E, out);
    loss_kernel<<<1, 256>>>(out);
}

// round 17
// speedup vs baseline: 2.6707x; 1.2518x over previous
#include <cuda_runtime.h>
#include <cuda_bf16.h>
#include <cuda_fp16.h>
#include <cstdint>
#include <math.h>

// queries [16,1024,256] f32 -> M=16384, embedding [8192,256] f32 -> N=8192
// Output (f32): [M indices][M*256 quantized_st][1 vq_loss]

#define M_TOTAL 16384
#define N_TOTAL 8192
#define KDIM    256
#define KC      512          // fp16 2-product: Q'=[hi|lo], E reads e_hi twice
#define BKC     64
#define NCHUNK  (KC / BKC)   // 8

#define BM 128
#define BN 128
#define NBLK (N_TOTAL / BN)  // 64 column blocks
#define LDA 72               // smem row stride (halves), padded

#define STAGE_BYTES (BM * LDA * 2)          // 18432 B per matrix stage
#define SMEM_DYN    (4 * STAGE_BYTES)       // A0,B0,A1,B1 = 73728 B

typedef unsigned long long u64;

// Scratch
__device__ float g_esq[N_TOTAL];
__device__ float g_qsq[M_TOTAL];
__device__ ulonglong2 g_btop[NBLK * M_TOTAL];
__device__ int   g_final[M_TOTAL];
__device__ float g_partial[M_TOTAL];
__device__ __half g_Qc[(size_t)M_TOTAL * KC];   // [hi(256) | lo(256)]
__device__ __half g_Eh[(size_t)N_TOTAL * KDIM]; // e_hi only

__device__ __forceinline__ unsigned float_ordered(float f) {
    unsigned u = __float_as_uint(f);
    return (u & 0x80000000u) ? ~u : (u | 0x80000000u);
}
__device__ __forceinline__ void ins2(u64 k, u64& m1, u64& m2) {
    if (k < m1) { m2 = m1; m1 = k; }
    else if (k < m2) { m2 = k; }
}
__device__ __forceinline__ void ins4(u64 k, u64* m) {
    if (k < m[3]) {
        if (k < m[1]) {
            if (k < m[0]) { m[3]=m[2]; m[2]=m[1]; m[1]=m[0]; m[0]=k; }
            else          { m[3]=m[2]; m[2]=m[1]; m[1]=k; }
        } else {
            if (k < m[2]) { m[3]=m[2]; m[2]=k; }
            else          { m[3]=k; }
        }
    }
}

__device__ __forceinline__ uint32_t smem_u32(const void* p) {
    uint32_t a;
    asm("{ .reg .u64 t; cvta.to.shared.u64 t, %1; cvt.u32.u64 %0, t; }"
        : "=r"(a) : "l"(p));
    return a;
}
__device__ __forceinline__ void cp16(uint32_t dst, const void* src) {
    asm volatile("cp.async.cg.shared.global [%0], [%1], 16;"
                 :: "r"(dst), "l"(src) : "memory");
}
#define CP_COMMIT() asm volatile("cp.async.commit_group;" ::: "memory")
#define CP_WAIT(n)  asm volatile("cp.async.wait_group %0;" :: "n"(n) : "memory")

__device__ __forceinline__ void ldm_x4(uint32_t* r, uint32_t addr) {
    asm volatile("ldmatrix.sync.aligned.m8n8.x4.shared.b16 {%0,%1,%2,%3}, [%4];"
                 : "=r"(r[0]), "=r"(r[1]), "=r"(r[2]), "=r"(r[3]) : "r"(addr));
}
__device__ __forceinline__ void mma16816(float* d, const uint32_t* a,
                                         uint32_t b0, uint32_t b1) {
    asm volatile(
        "mma.sync.aligned.m16n8k16.row.col.f32.f16.f16.f32 "
        "{%0,%1,%2,%3}, {%4,%5,%6,%7}, {%8,%9}, {%0,%1,%2,%3};"
        : "+f"(d[0]), "+f"(d[1]), "+f"(d[2]), "+f"(d[3])
        : "r"(a[0]), "r"(a[1]), "r"(a[2]), "r"(a[3]), "r"(b0), "r"(b1));
}

// ---------------------------------------------------------------------------
// fp16 hi/lo split for Q (concat-K), fp16 hi for E.
__global__ void convert_q_kernel(const float* __restrict__ Q) {
    int i = blockIdx.x * 256 + threadIdx.x;
    if (i >= M_TOTAL * KDIM) return;
    int m = i >> 8, c = i & 255;
    float x = Q[i];
    __half h = __float2half(x);
    __half l = __float2half(x - __half2float(h));
    size_t base = (size_t)m * KC + c;
    g_Qc[base]       = h;
    g_Qc[base + 256] = l;
}
__global__ void convert_e_kernel(const float* __restrict__ E) {
    int i = blockIdx.x * 256 + threadIdx.x;
    if (i >= N_TOTAL * KDIM) return;
    g_Eh[i] = __float2half(E[i]);
}

// ---------------------------------------------------------------------------
// Squared norms (warp per row; mul-then-add + xor tree — R5-proven)
__global__ void sqnorm_kernel(const float* __restrict__ X, int nrows, int which) {
    int row = blockIdx.x * 8 + (threadIdx.x >> 5);
    int lane = threadIdx.x & 31;
    if (row >= nrows) return;
    const float* x = X + (size_t)row * KDIM;
    float s = 0.f;
    #pragma unroll
    for (int c = lane; c < KDIM; c += 32) { float v = x[c]; float p = v * v; s = s + p; }
    #pragma unroll
    for (int off = 16; off; off >>= 1) s += __shfl_xor_sync(0xffffffffu, s, off);
    if (lane == 0) { if (which) g_qsq[row] = s; else g_esq[row] = s; }
}

// ---------------------------------------------------------------------------
// Raw mma.sync fp16 score GEMM (K=512 hi/lo) + register top-2 epilogue with
// cross-warp merge via smem (the R16 bug: 4 wn-warps each cover 32 cols and
// MUST be merged before writing g_btop).
__global__ __launch_bounds__(256, 2)
void score_mma_kernel() {
    extern __shared__ char dsm[];
    __shared__ float esq_s[BN];

    const int tid = threadIdx.x;
    const int wid = tid >> 5;
    const int lane = tid & 31;
    const int wm = wid >> 2;
    const int wn = wid & 3;
    const int rowBase = blockIdx.x * BM;
    const int colBase = blockIdx.y * BN;

    if (tid < BN) esq_s[tid] = g_esq[colBase + tid];

    const uint32_t asu[2] = { smem_u32(dsm),
                              smem_u32(dsm + 2 * STAGE_BYTES) };
    const uint32_t bsu[2] = { smem_u32(dsm + STAGE_BYTES),
                              smem_u32(dsm + 3 * STAGE_BYTES) };

    const __half* Ag = g_Qc + (size_t)rowBase * KC;
    const __half* Bg = g_Eh + (size_t)colBase * KDIM;

    // stage loads: 2 threads per row, 4 contiguous 16B segs each
    const int r4 = tid >> 1;
    const int sg = (tid & 1) * 4;
    auto load_stage = [&](int buf, int kc) {
        #pragma unroll
        for (int h = 0; h < 4; h++) {
            int seg = sg + h;
            cp16(asu[buf] + (uint32_t)(r4 * (LDA * 2) + seg * 16),
                 Ag + (size_t)r4 * KC + kc * BKC + seg * 8);
            cp16(bsu[buf] + (uint32_t)(r4 * (LDA * 2) + seg * 16),
                 Bg + (size_t)r4 * KDIM + (kc & 3) * BKC + seg * 8);
        }
    };

    float acc[4][4][4];   // [m-tile][n-tile][reg]
    #pragma unroll
    for (int i = 0; i < 4; i++)
        #pragma unroll
        for (int j = 0; j < 4; j++)
            #pragma unroll
            for (int rr = 0; rr < 4; rr++) acc[i][j][rr] = 0.f;

    // ldmatrix lane geometry (same for A and B tiles)
    const int lrow = lane & 15;            // row within 16
    const int lcol = (lane >> 4) << 3;     // 0 or 8 (k halves)

    load_stage(0, 0);
    CP_COMMIT();

    for (int kc = 0; kc < NCHUNK; kc++) {
        if (kc + 1 < NCHUNK) {
            load_stage((kc + 1) & 1, kc + 1);
            CP_COMMIT();
            CP_WAIT(1);
        } else {
            CP_WAIT(0);
        }
        __syncthreads();

        const uint32_t a_base = asu[kc & 1];
        const uint32_t b_base = bsu[kc & 1];

        #pragma unroll
        for (int ks = 0; ks < BKC / 16; ks++) {
            uint32_t ra[4][4];
            #pragma unroll
            for (int mt = 0; mt < 4; mt++) {
                uint32_t addr = a_base +
                    (uint32_t)(((wm * 64 + mt * 16 + lrow) * LDA + ks * 16 + lcol) * 2);
                ldm_x4(ra[mt], addr);
            }
            uint32_t rb[2][4];
            #pragma unroll
            for (int bp = 0; bp < 2; bp++) {
                uint32_t addr = b_base +
                    (uint32_t)(((wn * 32 + bp * 16 + lrow) * LDA + ks * 16 + lcol) * 2);
                ldm_x4(rb[bp], addr);
            }
            #pragma unroll
            for (int mt = 0; mt < 4; mt++)
                #pragma unroll
                for (int nt = 0; nt < 4; nt++)
                    mma16816(acc[mt][nt], ra[mt],
                             rb[nt >> 1][nt & 1], rb[nt >> 1][(nt & 1) + 2]);
        }
        __syncthreads();
    }

    // ---- Epilogue ----
    // Per-warp: top-2 over this warp's 32 columns per row (in registers),
    // stage to smem tops[row][wn], then merge the 4 wn slices per row.
    ulonglong2* tops = (ulonglong2*)dsm;   // [BM][4] = 8 KB (stages are dead)
    const int r = lane >> 2;
    const int cq = lane & 3;
    #pragma unroll
    for (int mt = 0; mt < 4; mt++) {
        u64 m1a = ~0ULL, m2a = ~0ULL;   // row r
        u64 m1b = ~0ULL, m2b = ~0ULL;   // row r+8
        #pragma unroll
        for (int nt = 0; nt < 4; nt++) {
            int col = wn * 32 + nt * 8 + cq * 2;
            float e0 = esq_s[col], e1 = esq_s[col + 1];
            float d0 = e0 - 2.0f * acc[mt][nt][0];
            float d1 = e1 - 2.0f * acc[mt][nt][1];
            float d2 = e0 - 2.0f * acc[mt][nt][2];
            float d3 = e1 - 2.0f * acc[mt][nt][3];
            unsigned g0 = (unsigned)(colBase + col);
            ins2(((u64)float_ordered(d0) << 32) | g0,       m1a, m2a);
            ins2(((u64)float_ordered(d1) << 32) | (g0 + 1), m1a, m2a);
            ins2(((u64)float_ordered(d2) << 32) | g0,       m1b, m2b);
            ins2(((u64)float_ordered(d3) << 32) | (g0 + 1), m1b, m2b);
        }
        #pragma unroll
        for (int off = 1; off < 4; off <<= 1) {
            u64 o;
            o = __shfl_xor_sync(0xffffffffu, m1a, off, 4); ins2(o, m1a, m2a);
            o = __shfl_xor_sync(0xffffffffu, m2a, off, 4); ins2(o, m1a, m2a);
            o = __shfl_xor_sync(0xffffffffu, m1b, off, 4); ins2(o, m1b, m2b);
            o = __shfl_xor_sync(0xffffffffu, m2b, off, 4); ins2(o, m1b, m2b);
        }
        if (cq == 0) {
            int lr = wm * 64 + mt * 16 + r;
            tops[lr * 4 + wn]       = make_ulonglong2(m1a, m2a);
            tops[(lr + 8) * 4 + wn] = make_ulonglong2(m1b, m2b);
        }
    }
    __syncthreads();

    if (tid < BM) {
        u64 m1 = ~0ULL, m2 = ~0ULL;
        #pragma unroll
        for (int w = 0; w < 4; w++) {
            ulonglong2 v = tops[tid * 4 + w];
            ins2(v.x, m1, m2);
            ins2(v.y, m1, m2);
        }
        g_btop[blockIdx.y * M_TOTAL + rowBase + tid] = make_ulonglong2(m1, m2);
    }
}

// ---------------------------------------------------------------------------
// Merge block top-2 -> global top-4; compensated-fp32 exact dots; emulate the
// reference's fp32 rounding: d = fl32( fl32(qsq+esq) - 2*dot ). (proven)
__global__ void refine_kernel(const float* __restrict__ Q, const float* __restrict__ E) {
    int warp = threadIdx.x >> 5;
    int lane = threadIdx.x & 31;
    int q = blockIdx.x * 8 + warp;

    u64 m[4] = {~0ULL, ~0ULL, ~0ULL, ~0ULL};
    #pragma unroll
    for (int b = lane; b < NBLK; b += 32) {
        ulonglong2 v = g_btop[b * M_TOTAL + q];
        ins4(v.x, m);
        ins4(v.y, m);
    }
    #pragma unroll
    for (int off = 16; off; off >>= 1) {
        #pragma unroll
        for (int t = 0; t < 4; t++) {
            u64 o = __shfl_xor_sync(0xffffffffu, m[t], off);
            ins4(o, m);
        }
    }

    const float* qr = Q + (size_t)q * KDIM;
    float dots[4];
    int   ns[4];
    #pragma unroll
    for (int t = 0; t < 4; t++) {
        int n = (int)(unsigned)(m[t] & 0xffffffffu);
        ns[t] = n;
        const float* e = E + (size_t)n * KDIM;
        float s = 0.f, c = 0.f, err = 0.f;
        #pragma unroll
        for (int cc = lane; cc < KDIM; cc += 32) {
            float qv = qr[cc], ev = e[cc];
            float p = qv * ev;
            float rr = fmaf(qv, ev, -p);
            float y = p - c;
            float tt = s + y;
            c = (tt - s) - y;
            s = tt;
            err += rr;
        }
        #pragma unroll
        for (int off = 16; off; off >>= 1) {
            s   += __shfl_xor_sync(0xffffffffu, s, off);
            err += __shfl_xor_sync(0xffffffffu, err, off);
        }
        dots[t] = s + err;
    }

    if (lane == 0) {
        float qsq = g_qsq[q];
        u64 best = ~0ULL;
        #pragma unroll
        for (int t = 0; t < 4; t++) {
            float A = qsq + g_esq[ns[t]];
            float d = fmaf(-2.0f, dots[t], A);
            u64 key = ((u64)float_ordered(d) << 32) | (unsigned)ns[t];
            best = (key < best) ? key : best;
        }
        g_final[q] = (int)(unsigned)(best & 0xffffffffu);
    }
}

// ---------------------------------------------------------------------------
__global__ void gather_kernel(const float* __restrict__ Q,
                              const float* __restrict__ E,
                              float* __restrict__ out) {
    int q = blockIdx.x;
    int idx = g_final[q];
    int c = threadIdx.x;

    float qv = Q[(size_t)q * KDIM + c];
    float ev = E[(size_t)idx * KDIM + c];
    out[(size_t)M_TOTAL + (size_t)q * KDIM + c] = qv + (ev - qv);

    float d = qv - ev;
    float s = d * d;
    #pragma unroll
    for (int off = 16; off; off >>= 1) s += __shfl_xor_sync(0xffffffffu, s, off);

    __shared__ float red[8];
    int lane = c & 31, warp = c >> 5;
    if (lane == 0) red[warp] = s;
    __syncthreads();
    if (c == 0) {
        float t = 0.f;
        #pragma unroll
        for (int w = 0; w < 8; w++) t += red[w];
        g_partial[q] = t;
        out[q] = (float)idx;
    }
}

// vq_loss = codebook + 0.25*commit = 1.25 * mean((q - quantized)^2)
__global__ void loss_kernel(float* __restrict__ out) {
    int tid = threadIdx.x;
    double s = 0.0;
    for (int i = tid; i < M_TOTAL; i += 256) s += (double)g_partial[i];
    #pragma unroll
    for (int off = 16; off; off >>= 1) s += __shfl_xor_sync(0xffffffffu, s, off);
    __shared__ double red[8];
    int lane = tid & 31, warp = tid >> 5;
    if (lane == 0) red[warp] = s;
    __syncthreads();
    if (tid == 0) {
        double t = 0.0;
        #pragma unroll
        for (int w = 0; w < 8; w++) t += red[w];
        double mean = t / (double)((size_t)M_TOTAL * KDIM);
        out[(size_t)M_TOTAL + (size_t)M_TOTAL * KDIM] = (float)(1.25 * mean);
    }
}

// ---------------------------------------------------------------------------
extern "C" void kernel_launch(void* const* d_in, const int* in_sizes, int n_in,
                              void* d_out, int out_size) {
    const float* Q = (const float*)d_in[0];
    const float* E = (const float*)d_in[1];
    float* out = (float*)d_out;

    cudaFuncSetAttribute(score_mma_kernel,
                         cudaFuncAttributeMaxDynamicSharedMemorySize, SMEM_DYN);

    convert_q_kernel<<<(M_TOTAL * KDIM + 255) / 256, 256>>>(Q);
    convert_e_kernel<<<(N_TOTAL * KDIM + 255) / 256, 256>>>(E);

    sqnorm_kernel<<<N_TOTAL / 8, 256>>>(E, N_TOTAL, 0);
    sqnorm_kernel<<<M_TOTAL / 8, 256>>>(Q, M_TOTAL, 1);

    dim3 grid(M_TOTAL / BM, N_TOTAL / BN);  // (128, 64)
    score_mma_kernel<<<grid, 256, SMEM_DYN>>>();

    refine_kernel<<<M_TOTAL / 8, 256>>>(Q, E);
    gather_kernel<<<M_TOTAL, KDIM>>>(Q, E, out);
    loss_kernel<<<1, 256>>>(out);
}